// round 3
// baseline (speedup 1.0000x reference)
#include <cuda_runtime.h>

#define TPB 416        // 32 batch elems * 13 nodes
#define NB  32         // batch elems per block
#define NGRID 1024     // 32768 / 32

#define ARENA_BYTES 6048
#define WREG_BYTES  16912
#define SMEM_TOTAL  (WREG_BYTES + NB * ARENA_BYTES)   // 210448

// packed f32x2 FMA (sm_100+): r = a*b + c per 32-bit half
__device__ __forceinline__ float2 ffma2(float2 a, float2 b, float2 c) {
    unsigned long long ua = *reinterpret_cast<unsigned long long*>(&a);
    unsigned long long ub = *reinterpret_cast<unsigned long long*>(&b);
    unsigned long long uc = *reinterpret_cast<unsigned long long*>(&c);
    unsigned long long ur;
    asm("fma.rn.f32x2 %0, %1, %2, %3;" : "=l"(ur) : "l"(ua), "l"(ub), "l"(uc));
    return *reinterpret_cast<float2*>(&ur);
}

__device__ __forceinline__ float getf2(const float2* v, int d) {
    return (d & 1) ? v[d >> 1].y : v[d >> 1].x;
}

__device__ __forceinline__ float lky(float v) { return fmaxf(v, 0.01f * v); }

__global__ __launch_bounds__(TPB, 1)
void vae_kernel(
    const float* __restrict__ adj,          // (B,4,13,13)
    const float* __restrict__ init_weight,  // (13,16)
    const float* __restrict__ eps_param,    // (4)
    const float* __restrict__ mlp_w0,       // (4,16,16)
    const float* __restrict__ mlp_b0,       // (4,16)
    const float* __restrict__ mlp_w1,       // (4,16,16)
    const float* __restrict__ mlp_b1,       // (4,16)
    const float* __restrict__ bn_in_gamma,  // (4,13)
    const float* __restrict__ bn_in_beta,
    const float* __restrict__ bn_in_mean,
    const float* __restrict__ bn_in_var,
    const float* __restrict__ bn_out_gamma,
    const float* __restrict__ bn_out_beta,
    const float* __restrict__ bn_out_mean,
    const float* __restrict__ bn_out_var,
    const float* __restrict__ fc1_w,        // (16,16)
    const float* __restrict__ fc1_b,        // (16)
    const float* __restrict__ fc2_w,
    const float* __restrict__ fc2_b,
    const float* __restrict__ dec_w,        // (4,16,16)
    const float* __restrict__ dec_b,        // (4,16)
    float* __restrict__ d_out)
{
    extern __shared__ char sm[];
    // ---- weight region (shared by all 32 batch elems in block) ----
    float2* w0t   = (float2*)(sm + 0);       // [4][16][8] pairs over d'
    float2* w1t   = (float2*)(sm + 4096);    // [4][16][8]
    float2* b0p   = (float2*)(sm + 8192);    // [4][8]
    float2* b1p   = (float2*)(sm + 8448);    // [4][8]
    float2* winit = (float2*)(sm + 8704);    // [13][8] pairs over d
    float2* fc1t  = (float2*)(sm + 9536);    // [16][8]
    float2* fc2t  = (float2*)(sm + 10560);   // [16][8]
    float2* fc1bp = (float2*)(sm + 11584);   // [8]
    float2* fc2bp = (float2*)(sm + 11648);   // [8]
    float2* dect  = (float2*)(sm + 11712);   // [4][16][8] pairs over d
    float2* decbp = (float2*)(sm + 15808);   // [4][8]
    float*  bnin_s  = (float*)(sm + 16064);  // [4][13]
    float*  bnin_t  = (float*)(sm + 16272);
    float*  bnout_s = (float*)(sm + 16480);
    float*  bnout_t = (float*)(sm + 16688);
    float*  eps1    = (float*)(sm + 16896);  // [4]
    char*   arenas  = sm + WREG_BYTES;

    const int t = threadIdx.x;

    // ---- stage transposed/packed weights ----
    for (int idx = t; idx < 512; idx += TPB) {          // 4*16*8
        int l = idx >> 7, r = idx & 127, d = r >> 3, j = r & 7;
        const float* w = mlp_w0 + l * 256;
        w0t[idx] = make_float2(w[(2*j)*16 + d], w[(2*j+1)*16 + d]);
        const float* w1 = mlp_w1 + l * 256;
        w1t[idx] = make_float2(w1[(2*j)*16 + d], w1[(2*j+1)*16 + d]);
        const float* dw = dec_w + l * 256;              // k = l, lsum = d
        dect[idx] = make_float2(dw[(2*j)*16 + d], dw[(2*j+1)*16 + d]);
    }
    for (int idx = t; idx < 128; idx += TPB) {          // 16*8
        int d = idx >> 3, j = idx & 7;
        fc1t[idx] = make_float2(fc1_w[(2*j)*16 + d], fc1_w[(2*j+1)*16 + d]);
        fc2t[idx] = make_float2(fc2_w[(2*j)*16 + d], fc2_w[(2*j+1)*16 + d]);
    }
    for (int idx = t; idx < 104; idx += TPB) {          // 13*8
        int m = idx >> 3, j = idx & 7;
        winit[idx] = make_float2(init_weight[m*16 + 2*j], init_weight[m*16 + 2*j + 1]);
    }
    for (int idx = t; idx < 32; idx += TPB) {           // 4*8
        int l = idx >> 3, j = idx & 7;
        b0p[idx]   = make_float2(mlp_b0[l*16 + 2*j], mlp_b0[l*16 + 2*j + 1]);
        b1p[idx]   = make_float2(mlp_b1[l*16 + 2*j], mlp_b1[l*16 + 2*j + 1]);
        decbp[idx] = make_float2(dec_b[l*16 + 2*j],  dec_b[l*16 + 2*j + 1]);
    }
    if (t < 8) {
        fc1bp[t] = make_float2(fc1_b[2*t], fc1_b[2*t + 1]);
        fc2bp[t] = make_float2(fc2_b[2*t], fc2_b[2*t + 1]);
    }
    for (int idx = t; idx < 52; idx += TPB) {           // 4*13 BN fold
        float s = bn_in_gamma[idx] * rsqrtf(bn_in_var[idx] + 1e-5f);
        bnin_s[idx] = s;
        bnin_t[idx] = bn_in_beta[idx] - bn_in_mean[idx] * s;
        float so = bn_out_gamma[idx] * rsqrtf(bn_out_var[idx] + 1e-5f);
        bnout_s[idx] = so;
        bnout_t[idx] = bn_out_beta[idx] - bn_out_mean[idx] * so;
    }
    if (t < 4) eps1[t] = 1.0f + eps_param[t];

    // ---- load adj (coalesced float4) into per-b arenas ----
    const float4* adjg = (const float4*)(adj + (size_t)blockIdx.x * NB * 676);
    for (int i = t; i < NB * 169; i += TPB) {           // 13 iters exactly
        int b = i / 169, q = i - b * 169;
        *(float4*)(arenas + b * ARENA_BYTES + q * 16) = adjg[i];
    }
    __syncthreads();

    // ---- per-thread: (bl, n) ----
    const int bl = t / 13;
    const int n  = t - bl * 13;
    float*  adjS  = (float*)(arenas + bl * ARENA_BYTES);          // [g*169 + n*13 + m]
    float2* xrow0 = (float2*)(arenas + bl * ARENA_BYTES + 2720);  // [m*8 + j]

    // x init: asum over channels, then @ init_weight
    float asum[13];
#pragma unroll
    for (int m = 0; m < 13; m++) {
        int o = n * 13 + m;
        asum[m] = adjS[o] + adjS[169 + o] + adjS[338 + o] + adjS[507 + o];
    }
    float2 x2[8];
#pragma unroll
    for (int j = 0; j < 8; j++) x2[j] = make_float2(0.f, 0.f);
#pragma unroll
    for (int m = 0; m < 13; m++) {
        float2 ap = make_float2(asum[m], asum[m]);
#pragma unroll
        for (int j = 0; j < 8; j++) x2[j] = ffma2(ap, winit[m * 8 + j], x2[j]);
    }
#pragma unroll
    for (int j = 0; j < 8; j++) xrow0[n * 8 + j] = x2[j];
    __syncthreads();

    // ---- 4 GIN layers ----
#pragma unroll
    for (int l = 0; l < 4; l++) {
        // neighbor: group g = d/4 uses adj channel g
        float2 nb2[8];
#pragma unroll
        for (int j = 0; j < 8; j++) nb2[j] = make_float2(0.f, 0.f);
#pragma unroll
        for (int m = 0; m < 13; m++) {
            int o = n * 13 + m;
            float a0 = adjS[o], a1 = adjS[169 + o], a2v = adjS[338 + o], a3 = adjS[507 + o];
            float2 ag[4] = { make_float2(a0,a0), make_float2(a1,a1),
                             make_float2(a2v,a2v), make_float2(a3,a3) };
            const float2* xm = &xrow0[m * 8];
#pragma unroll
            for (int j = 0; j < 8; j++) nb2[j] = ffma2(ag[j >> 1], xm[j], nb2[j]);
        }
        float e = eps1[l];
        float2 ep = make_float2(e, e);
        float2 agg2[8];
#pragma unroll
        for (int j = 0; j < 8; j++) agg2[j] = ffma2(ep, x2[j], nb2[j]);
        __syncthreads();   // all x reads done before x rewrite below

        // h1 = agg @ w0^T + b0 -> BN_in -> leaky
        float2 h2[8];
#pragma unroll
        for (int j = 0; j < 8; j++) h2[j] = b0p[l * 8 + j];
#pragma unroll
        for (int d = 0; d < 16; d++) {
            float a = getf2(agg2, d);
            float2 ap = make_float2(a, a);
            const float2* wr = &w0t[l * 128 + d * 8];
#pragma unroll
            for (int j = 0; j < 8; j++) h2[j] = ffma2(ap, wr[j], h2[j]);
        }
        {
            float s = bnin_s[l * 13 + n], ts = bnin_t[l * 13 + n];
            float2 sp = make_float2(s, s), tp = make_float2(ts, ts);
#pragma unroll
            for (int j = 0; j < 8; j++) {
                h2[j] = ffma2(sp, h2[j], tp);
                h2[j].x = lky(h2[j].x); h2[j].y = lky(h2[j].y);
            }
        }
        // out = h1 @ w1^T + b1 -> BN_out -> leaky -> new x
        float2 o2[8];
#pragma unroll
        for (int j = 0; j < 8; j++) o2[j] = b1p[l * 8 + j];
#pragma unroll
        for (int d = 0; d < 16; d++) {
            float a = getf2(h2, d);
            float2 ap = make_float2(a, a);
            const float2* wr = &w1t[l * 128 + d * 8];
#pragma unroll
            for (int j = 0; j < 8; j++) o2[j] = ffma2(ap, wr[j], o2[j]);
        }
        {
            float s = bnout_s[l * 13 + n], ts = bnout_t[l * 13 + n];
            float2 sp = make_float2(s, s), tp = make_float2(ts, ts);
#pragma unroll
            for (int j = 0; j < 8; j++) {
                o2[j] = ffma2(sp, o2[j], tp);
                o2[j].x = lky(o2[j].x); o2[j].y = lky(o2[j].y);
                x2[j] = o2[j];
            }
        }
#pragma unroll
        for (int j = 0; j < 8; j++) xrow0[n * 8 + j] = x2[j];
        __syncthreads();
    }

    // ---- fc heads: mu, logvar ----
    float2 mu2[8], lv2[8];
#pragma unroll
    for (int j = 0; j < 8; j++) { mu2[j] = fc1bp[j]; lv2[j] = fc2bp[j]; }
#pragma unroll
    for (int d = 0; d < 16; d++) {
        float a = getf2(x2, d);
        float2 ap = make_float2(a, a);
#pragma unroll
        for (int j = 0; j < 8; j++) {
            mu2[j] = ffma2(ap, fc1t[d * 8 + j], mu2[j]);
            lv2[j] = ffma2(ap, fc2t[d * 8 + j], lv2[j]);
        }
    }
    {
        size_t bg = (size_t)blockIdx.x * NB + bl;
        float* muo = d_out + 22151168ull + (bg * 13 + n) * 16;
        float* lvo = d_out + 28966912ull + (bg * 13 + n) * 16;
#pragma unroll
        for (int q = 0; q < 4; q++) {
            ((float4*)muo)[q] = make_float4(mu2[2*q].x, mu2[2*q].y, mu2[2*q+1].x, mu2[2*q+1].y);
            ((float4*)lvo)[q] = make_float4(lv2[2*q].x, lv2[2*q].y, lv2[2*q+1].x, lv2[2*q+1].y);
        }
    }

    // ---- decoder: temp[k][n][d] = z @ dec_w[k]^T + dec_b[k]  (z = mu) ----
    // temp overlays the (now dead) adj region of the arena
    float2* tS = (float2*)(arenas + bl * ARENA_BYTES);  // [k*104 + m*8 + j]
#pragma unroll
    for (int k = 0; k < 4; k++) {
        float2 acc[8];
#pragma unroll
        for (int j = 0; j < 8; j++) acc[j] = decbp[k * 8 + j];
#pragma unroll
        for (int d = 0; d < 16; d++) {
            float a = getf2(mu2, d);
            float2 ap = make_float2(a, a);
            const float2* wr = &dect[k * 128 + d * 8];
#pragma unroll
            for (int j = 0; j < 8; j++) acc[j] = ffma2(ap, wr[j], acc[j]);
        }
#pragma unroll
        for (int j = 0; j < 8; j++) tS[k * 104 + n * 8 + j] = acc[j];
    }
    __syncthreads();

    // ---- recon[k][n][m] = relu(<temp[k][n], temp[k][m]>), staged in shared ----
    float* reconS = (float*)(arenas + bl * ARENA_BYTES + 3328);  // [k*169 + n*13 + m]
#pragma unroll
    for (int k = 0; k < 4; k++) {
        float2 tn[8];
#pragma unroll
        for (int j = 0; j < 8; j++) tn[j] = tS[k * 104 + n * 8 + j];
#pragma unroll
        for (int m = 0; m < 13; m++) {
            const float2* tm = &tS[k * 104 + m * 8];
            float2 acc = make_float2(0.f, 0.f);
#pragma unroll
            for (int j = 0; j < 8; j++) acc = ffma2(tn[j], tm[j], acc);
            float v = acc.x + acc.y;
            reconS[k * 169 + n * 13 + m] = fmaxf(v, 0.0f);
        }
    }
    __syncthreads();

    // ---- coalesced recon flush (float4) ----
    {
        float4* outg = (float4*)d_out;
        size_t base4 = (size_t)blockIdx.x * NB * 169;
        for (int i = t; i < NB * 169; i += TPB) {       // 13 iters exactly
            int b = i / 169, q = i - b * 169;
            outg[base4 + i] = *(const float4*)(arenas + b * ARENA_BYTES + 3328 + q * 16);
        }
    }
}

extern "C" void kernel_launch(void* const* d_in, const int* in_sizes, int n_in,
                              void* d_out, int out_size) {
    (void)in_sizes; (void)n_in; (void)out_size;
    cudaFuncSetAttribute(vae_kernel, cudaFuncAttributeMaxDynamicSharedMemorySize, SMEM_TOTAL);
    vae_kernel<<<NGRID, TPB, SMEM_TOTAL>>>(
        (const float*)d_in[0],  (const float*)d_in[1],  (const float*)d_in[2],
        (const float*)d_in[3],  (const float*)d_in[4],  (const float*)d_in[5],
        (const float*)d_in[6],  (const float*)d_in[7],  (const float*)d_in[8],
        (const float*)d_in[9],  (const float*)d_in[10], (const float*)d_in[11],
        (const float*)d_in[12], (const float*)d_in[13], (const float*)d_in[14],
        (const float*)d_in[15], (const float*)d_in[16], (const float*)d_in[17],
        (const float*)d_in[18], (const float*)d_in[19], (const float*)d_in[20],
        (float*)d_out);
}

// round 4
// speedup vs baseline: 1.0102x; 1.0102x over previous
#include <cuda_runtime.h>

#define TPB 416        // 32 batch elems * 13 nodes
#define NB  32         // batch elems per block
#define NGRID 1024     // 32768 / 32

#define ARENA_BYTES 6048
#define WREG_BYTES  16912
#define SMEM_TOTAL  (WREG_BYTES + NB * ARENA_BYTES)   // 210448

// packed f32x2 FMA (sm_100+): r = a*b + c per 32-bit half
__device__ __forceinline__ float2 ffma2(float2 a, float2 b, float2 c) {
    unsigned long long ua = *reinterpret_cast<unsigned long long*>(&a);
    unsigned long long ub = *reinterpret_cast<unsigned long long*>(&b);
    unsigned long long uc = *reinterpret_cast<unsigned long long*>(&c);
    unsigned long long ur;
    asm("fma.rn.f32x2 %0, %1, %2, %3;" : "=l"(ur) : "l"(ua), "l"(ub), "l"(uc));
    return *reinterpret_cast<float2*>(&ur);
}

__device__ __forceinline__ float2 lo2(float4 v) { return make_float2(v.x, v.y); }
__device__ __forceinline__ float2 hi2(float4 v) { return make_float2(v.z, v.w); }

__device__ __forceinline__ float getf2(const float2* v, int d) {
    return (d & 1) ? v[d >> 1].y : v[d >> 1].x;
}

__device__ __forceinline__ float lky(float v) { return fmaxf(v, 0.01f * v); }

// 16x16 matmul: out2[8] (pairs over d') += sum_d in(d) * Wq[d][4 float4]
// Wq float4 layout: component c of q-th float4 at row d = W[4q+c][d]
__device__ __forceinline__ void mm16(float2* out2, const float2* in2, const float4* Wq) {
#pragma unroll
    for (int d = 0; d < 16; d++) {
        float a = getf2(in2, d);
        float2 ap = make_float2(a, a);
        float4 q0 = Wq[d * 4 + 0];
        float4 q1 = Wq[d * 4 + 1];
        float4 q2 = Wq[d * 4 + 2];
        float4 q3 = Wq[d * 4 + 3];
        out2[0] = ffma2(ap, lo2(q0), out2[0]);
        out2[1] = ffma2(ap, hi2(q0), out2[1]);
        out2[2] = ffma2(ap, lo2(q1), out2[2]);
        out2[3] = ffma2(ap, hi2(q1), out2[3]);
        out2[4] = ffma2(ap, lo2(q2), out2[4]);
        out2[5] = ffma2(ap, hi2(q2), out2[5]);
        out2[6] = ffma2(ap, lo2(q3), out2[6]);
        out2[7] = ffma2(ap, hi2(q3), out2[7]);
    }
}

__global__ __launch_bounds__(TPB, 1)
void vae_kernel(
    const float* __restrict__ adj,          // (B,4,13,13)
    const float* __restrict__ init_weight,  // (13,16)
    const float* __restrict__ eps_param,    // (4)
    const float* __restrict__ mlp_w0,       // (4,16,16)
    const float* __restrict__ mlp_b0,       // (4,16)
    const float* __restrict__ mlp_w1,       // (4,16,16)
    const float* __restrict__ mlp_b1,       // (4,16)
    const float* __restrict__ bn_in_gamma,  // (4,13)
    const float* __restrict__ bn_in_beta,
    const float* __restrict__ bn_in_mean,
    const float* __restrict__ bn_in_var,
    const float* __restrict__ bn_out_gamma,
    const float* __restrict__ bn_out_beta,
    const float* __restrict__ bn_out_mean,
    const float* __restrict__ bn_out_var,
    const float* __restrict__ fc1_w,        // (16,16)
    const float* __restrict__ fc1_b,        // (16)
    const float* __restrict__ fc2_w,
    const float* __restrict__ fc2_b,
    const float* __restrict__ dec_w,        // (4,16,16)
    const float* __restrict__ dec_b,        // (4,16)
    float* __restrict__ d_out)
{
    extern __shared__ char sm[];
    // ---- weight region (shared by all 32 batch elems in block) ----
    float4* w0q   = (float4*)(sm + 0);      // [4][16][4]
    float4* w1q   = (float4*)(sm + 4096);   // [4][16][4]
    float4* decq  = (float4*)(sm + 8192);   // [4][16][4]
    float4* fc1q  = (float4*)(sm + 12288);  // [16][4]
    float4* fc2q  = (float4*)(sm + 13312);  // [16][4]
    float4* b0q   = (float4*)(sm + 14336);  // [4][4]
    float4* b1q   = (float4*)(sm + 14592);  // [4][4]
    float4* decbq = (float4*)(sm + 14848);  // [4][4]
    float4* fc1bq = (float4*)(sm + 15104);  // [4]
    float4* fc2bq = (float4*)(sm + 15168);  // [4]
    float2* bninq = (float2*)(sm + 15232);  // [4][13] (s,t)
    float2* bnoutq= (float2*)(sm + 15648);  // [4][13] (s,t)
    float4* winitq= (float4*)(sm + 16064);  // [13][4]
    float*  eps1  = (float*)(sm + 16896);   // [4]
    char*   arenas = sm + WREG_BYTES;

    const int t = threadIdx.x;

    // ---- stage transposed/packed weights ----
    for (int idx = t; idx < 256; idx += TPB) {          // 4*16*4
        int l = idx >> 6, d = (idx >> 2) & 15, q = idx & 3;
        const float* w  = mlp_w0 + l * 256;
        const float* w1 = mlp_w1 + l * 256;
        const float* dw = dec_w  + l * 256;
        w0q[idx]  = make_float4(w [(4*q+0)*16+d], w [(4*q+1)*16+d], w [(4*q+2)*16+d], w [(4*q+3)*16+d]);
        w1q[idx]  = make_float4(w1[(4*q+0)*16+d], w1[(4*q+1)*16+d], w1[(4*q+2)*16+d], w1[(4*q+3)*16+d]);
        decq[idx] = make_float4(dw[(4*q+0)*16+d], dw[(4*q+1)*16+d], dw[(4*q+2)*16+d], dw[(4*q+3)*16+d]);
    }
    for (int idx = t; idx < 64; idx += TPB) {           // 16*4
        int d = idx >> 2, q = idx & 3;
        fc1q[idx] = make_float4(fc1_w[(4*q+0)*16+d], fc1_w[(4*q+1)*16+d], fc1_w[(4*q+2)*16+d], fc1_w[(4*q+3)*16+d]);
        fc2q[idx] = make_float4(fc2_w[(4*q+0)*16+d], fc2_w[(4*q+1)*16+d], fc2_w[(4*q+2)*16+d], fc2_w[(4*q+3)*16+d]);
    }
    for (int idx = t; idx < 52; idx += TPB)             // 13*4
        winitq[idx] = ((const float4*)init_weight)[idx];
    for (int idx = t; idx < 16; idx += TPB) {           // 4*4
        b0q[idx]   = ((const float4*)mlp_b0)[idx];
        b1q[idx]   = ((const float4*)mlp_b1)[idx];
        decbq[idx] = ((const float4*)dec_b)[idx];
    }
    if (t < 4) {
        fc1bq[t] = ((const float4*)fc1_b)[t];
        fc2bq[t] = ((const float4*)fc2_b)[t];
        eps1[t]  = 1.0f + eps_param[t];
    }
    for (int idx = t; idx < 52; idx += TPB) {           // 4*13 BN fold
        float s = bn_in_gamma[idx] * rsqrtf(bn_in_var[idx] + 1e-5f);
        bninq[idx] = make_float2(s, bn_in_beta[idx] - bn_in_mean[idx] * s);
        float so = bn_out_gamma[idx] * rsqrtf(bn_out_var[idx] + 1e-5f);
        bnoutq[idx] = make_float2(so, bn_out_beta[idx] - bn_out_mean[idx] * so);
    }

    // ---- load adj (coalesced float4) into per-b arenas ----
    const float4* adjg = (const float4*)(adj + (size_t)blockIdx.x * NB * 676);
    for (int i = t; i < NB * 169; i += TPB) {           // 13 iters exactly
        int b = i / 169, q = i - b * 169;
        *(float4*)(arenas + b * ARENA_BYTES + q * 16) = adjg[i];
    }
    __syncthreads();

    // ---- per-thread: (bl, n) ----
    const int bl = t / 13;
    const int n  = t - bl * 13;
    char*   arena = arenas + bl * ARENA_BYTES;
    float*  adjS  = (float*)arena;                 // [g*169 + n*13 + m]
    float4* xb0   = (float4*)(arena + 2704);       // [13][4]
    float4* xb1   = (float4*)(arena + 3536);       // [13][4]

    // x init: asum over channels, then @ init_weight
    float asum[13];
#pragma unroll
    for (int m = 0; m < 13; m++) {
        int o = n * 13 + m;
        asum[m] = adjS[o] + adjS[169 + o] + adjS[338 + o] + adjS[507 + o];
    }
    float2 x2[8];
#pragma unroll
    for (int j = 0; j < 8; j++) x2[j] = make_float2(0.f, 0.f);
#pragma unroll
    for (int m = 0; m < 13; m++) {
        float2 ap = make_float2(asum[m], asum[m]);
        float4 q0 = winitq[m*4+0], q1 = winitq[m*4+1], q2 = winitq[m*4+2], q3 = winitq[m*4+3];
        x2[0] = ffma2(ap, lo2(q0), x2[0]);  x2[1] = ffma2(ap, hi2(q0), x2[1]);
        x2[2] = ffma2(ap, lo2(q1), x2[2]);  x2[3] = ffma2(ap, hi2(q1), x2[3]);
        x2[4] = ffma2(ap, lo2(q2), x2[4]);  x2[5] = ffma2(ap, hi2(q2), x2[5]);
        x2[6] = ffma2(ap, lo2(q3), x2[6]);  x2[7] = ffma2(ap, hi2(q3), x2[7]);
    }
#pragma unroll
    for (int q = 0; q < 4; q++)
        xb0[n*4+q] = make_float4(x2[2*q].x, x2[2*q].y, x2[2*q+1].x, x2[2*q+1].y);
    __syncthreads();

    // ---- 4 GIN layers (double-buffered x rows: one sync per layer) ----
#pragma unroll
    for (int l = 0; l < 4; l++) {
        const float4* xrd = (l & 1) ? xb1 : xb0;
        float4*       xwr = (l & 1) ? xb0 : xb1;

        // neighbor: group g = d/4 uses adj channel g
        float2 nb2[8];
#pragma unroll
        for (int j = 0; j < 8; j++) nb2[j] = make_float2(0.f, 0.f);
#pragma unroll
        for (int m = 0; m < 13; m++) {
            int o = n * 13 + m;
            float a0 = adjS[o], a1 = adjS[169 + o], a2v = adjS[338 + o], a3 = adjS[507 + o];
            float2 g0 = make_float2(a0, a0), g1 = make_float2(a1, a1);
            float2 g2 = make_float2(a2v, a2v), g3 = make_float2(a3, a3);
            float4 m0 = xrd[m*4+0], m1 = xrd[m*4+1], m2 = xrd[m*4+2], m3 = xrd[m*4+3];
            nb2[0] = ffma2(g0, lo2(m0), nb2[0]);  nb2[1] = ffma2(g0, hi2(m0), nb2[1]);
            nb2[2] = ffma2(g1, lo2(m1), nb2[2]);  nb2[3] = ffma2(g1, hi2(m1), nb2[3]);
            nb2[4] = ffma2(g2, lo2(m2), nb2[4]);  nb2[5] = ffma2(g2, hi2(m2), nb2[5]);
            nb2[6] = ffma2(g3, lo2(m3), nb2[6]);  nb2[7] = ffma2(g3, hi2(m3), nb2[7]);
        }
        float e = eps1[l];
        float2 ep = make_float2(e, e);
        float2 agg2[8];
#pragma unroll
        for (int j = 0; j < 8; j++) agg2[j] = ffma2(ep, x2[j], nb2[j]);

        // h1 = agg @ w0^T + b0 -> BN_in -> leaky
        float2 h2[8];
        {
            float4 c0 = b0q[l*4+0], c1 = b0q[l*4+1], c2 = b0q[l*4+2], c3 = b0q[l*4+3];
            h2[0] = lo2(c0); h2[1] = hi2(c0); h2[2] = lo2(c1); h2[3] = hi2(c1);
            h2[4] = lo2(c2); h2[5] = hi2(c2); h2[6] = lo2(c3); h2[7] = hi2(c3);
        }
        mm16(h2, agg2, &w0q[l * 64]);
        {
            float2 st = bninq[l * 13 + n];
            float2 sp = make_float2(st.x, st.x), tp = make_float2(st.y, st.y);
#pragma unroll
            for (int j = 0; j < 8; j++) {
                h2[j] = ffma2(sp, h2[j], tp);
                h2[j].x = lky(h2[j].x); h2[j].y = lky(h2[j].y);
            }
        }
        // out = h1 @ w1^T + b1 -> BN_out -> leaky -> new x
        float2 o2[8];
        {
            float4 c0 = b1q[l*4+0], c1 = b1q[l*4+1], c2 = b1q[l*4+2], c3 = b1q[l*4+3];
            o2[0] = lo2(c0); o2[1] = hi2(c0); o2[2] = lo2(c1); o2[3] = hi2(c1);
            o2[4] = lo2(c2); o2[5] = hi2(c2); o2[6] = lo2(c3); o2[7] = hi2(c3);
        }
        mm16(o2, h2, &w1q[l * 64]);
        {
            float2 st = bnoutq[l * 13 + n];
            float2 sp = make_float2(st.x, st.x), tp = make_float2(st.y, st.y);
#pragma unroll
            for (int j = 0; j < 8; j++) {
                o2[j] = ffma2(sp, o2[j], tp);
                o2[j].x = lky(o2[j].x); o2[j].y = lky(o2[j].y);
                x2[j] = o2[j];
            }
        }
        if (l < 3) {
#pragma unroll
            for (int q = 0; q < 4; q++)
                xwr[n*4+q] = make_float4(x2[2*q].x, x2[2*q].y, x2[2*q+1].x, x2[2*q+1].y);
            __syncthreads();
        }
    }

    // ---- fc heads: mu, logvar ----
    float2 mu2[8], lv2[8];
    {
        float4 c0 = fc1bq[0], c1 = fc1bq[1], c2 = fc1bq[2], c3 = fc1bq[3];
        mu2[0] = lo2(c0); mu2[1] = hi2(c0); mu2[2] = lo2(c1); mu2[3] = hi2(c1);
        mu2[4] = lo2(c2); mu2[5] = hi2(c2); mu2[6] = lo2(c3); mu2[7] = hi2(c3);
        float4 d0 = fc2bq[0], d1 = fc2bq[1], d2 = fc2bq[2], d3 = fc2bq[3];
        lv2[0] = lo2(d0); lv2[1] = hi2(d0); lv2[2] = lo2(d1); lv2[3] = hi2(d1);
        lv2[4] = lo2(d2); lv2[5] = hi2(d2); lv2[6] = lo2(d3); lv2[7] = hi2(d3);
    }
    mm16(mu2, x2, fc1q);
    mm16(lv2, x2, fc2q);
    {
        size_t bg = (size_t)blockIdx.x * NB + bl;
        float* muo = d_out + 22151168ull + (bg * 13 + n) * 16;
        float* lvo = d_out + 28966912ull + (bg * 13 + n) * 16;
#pragma unroll
        for (int q = 0; q < 4; q++) {
            ((float4*)muo)[q] = make_float4(mu2[2*q].x, mu2[2*q].y, mu2[2*q+1].x, mu2[2*q+1].y);
            ((float4*)lvo)[q] = make_float4(lv2[2*q].x, lv2[2*q].y, lv2[2*q+1].x, lv2[2*q+1].y);
        }
    }

    // Fence: layer-3 adj reads + xb1 reads must complete before tS/recon overlay
    __syncthreads();

    // ---- decoder: temp[k][n][d] = mu @ dec_w[k]^T + dec_b[k] ----
    float4* tS = (float4*)arena;   // [k*52 + m*4 + q], overlays adj + xb0
#pragma unroll
    for (int k = 0; k < 4; k++) {
        float2 acc[8];
        {
            float4 c0 = decbq[k*4+0], c1 = decbq[k*4+1], c2 = decbq[k*4+2], c3 = decbq[k*4+3];
            acc[0] = lo2(c0); acc[1] = hi2(c0); acc[2] = lo2(c1); acc[3] = hi2(c1);
            acc[4] = lo2(c2); acc[5] = hi2(c2); acc[6] = lo2(c3); acc[7] = hi2(c3);
        }
        mm16(acc, mu2, &decq[k * 64]);
#pragma unroll
        for (int q = 0; q < 4; q++)
            tS[k*52 + n*4 + q] = make_float4(acc[2*q].x, acc[2*q].y, acc[2*q+1].x, acc[2*q+1].y);
    }
    __syncthreads();

    // ---- recon[k][n][m] = relu(<temp[k][n], temp[k][m]>), staged in shared ----
    float* reconS = (float*)(arena + 3328);  // [k*169 + n*13 + m]
#pragma unroll
    for (int k = 0; k < 4; k++) {
        float2 tn[8];
        {
            float4 q0 = tS[k*52+n*4+0], q1 = tS[k*52+n*4+1], q2 = tS[k*52+n*4+2], q3 = tS[k*52+n*4+3];
            tn[0] = lo2(q0); tn[1] = hi2(q0); tn[2] = lo2(q1); tn[3] = hi2(q1);
            tn[4] = lo2(q2); tn[5] = hi2(q2); tn[6] = lo2(q3); tn[7] = hi2(q3);
        }
#pragma unroll
        for (int m = 0; m < 13; m++) {
            float4 q0 = tS[k*52+m*4+0], q1 = tS[k*52+m*4+1], q2 = tS[k*52+m*4+2], q3 = tS[k*52+m*4+3];
            float2 acc = make_float2(0.f, 0.f);
            acc = ffma2(tn[0], lo2(q0), acc);  acc = ffma2(tn[1], hi2(q0), acc);
            acc = ffma2(tn[2], lo2(q1), acc);  acc = ffma2(tn[3], hi2(q1), acc);
            acc = ffma2(tn[4], lo2(q2), acc);  acc = ffma2(tn[5], hi2(q2), acc);
            acc = ffma2(tn[6], lo2(q3), acc);  acc = ffma2(tn[7], hi2(q3), acc);
            float v = acc.x + acc.y;
            reconS[k * 169 + n * 13 + m] = fmaxf(v, 0.0f);
        }
    }
    __syncthreads();

    // ---- coalesced recon flush (float4) ----
    {
        float4* outg = (float4*)d_out;
        size_t base4 = (size_t)blockIdx.x * NB * 169;
        for (int i = t; i < NB * 169; i += TPB) {       // 13 iters exactly
            int b = i / 169, q = i - b * 169;
            outg[base4 + i] = *(const float4*)(arenas + b * ARENA_BYTES + 3328 + q * 16);
        }
    }
}

extern "C" void kernel_launch(void* const* d_in, const int* in_sizes, int n_in,
                              void* d_out, int out_size) {
    (void)in_sizes; (void)n_in; (void)out_size;
    cudaFuncSetAttribute(vae_kernel, cudaFuncAttributeMaxDynamicSharedMemorySize, SMEM_TOTAL);
    vae_kernel<<<NGRID, TPB, SMEM_TOTAL>>>(
        (const float*)d_in[0],  (const float*)d_in[1],  (const float*)d_in[2],
        (const float*)d_in[3],  (const float*)d_in[4],  (const float*)d_in[5],
        (const float*)d_in[6],  (const float*)d_in[7],  (const float*)d_in[8],
        (const float*)d_in[9],  (const float*)d_in[10], (const float*)d_in[11],
        (const float*)d_in[12], (const float*)d_in[13], (const float*)d_in[14],
        (const float*)d_in[15], (const float*)d_in[16], (const float*)d_in[17],
        (const float*)d_in[18], (const float*)d_in[19], (const float*)d_in[20],
        (float*)d_out);
}